// round 12
// baseline (speedup 1.0000x reference)
#include <cuda_runtime.h>

#define IMG 512
#define TW 32
#define TH 32
#define IW 42
#define IH 42
#define NQIN 21                    // input col-pairs (quads) per row
#define NQOUT 16                   // output col-pairs per row
#define ROWOUT (NQOUT * 4)         // 64 floats per hh row
#define NQTOT (IH * NQIN)          // 882 staged quads
#define NPIX (16LL * 3 * 512 * 512)
#define GRID_X 16
#define GRID_Y 16
#define GRID_Z 48
#define GRID_TOTAL (GRID_X * GRID_Y * GRID_Z)

typedef unsigned long long u64;

__device__ double g_sum;
__device__ unsigned int g_count;

// Gaussian(sigma=1.5, K=11) weights, normalized — compile-time constants.
#define WV0 0.00102838f
#define WV1 0.00759876f
#define WV2 0.03600077f
#define WV3 0.10936069f
#define WV4 0.21300553f
#define WV5 0.26601172f

__device__ __forceinline__ u64 pack2(float lo, float hi) {
    u64 r; asm("mov.b64 %0,{%1,%2};" : "=l"(r) : "f"(lo), "f"(hi)); return r;
}
__device__ __forceinline__ void unpack2(u64 v, float& lo, float& hi) {
    asm("mov.b64 {%0,%1},%2;" : "=f"(lo), "=f"(hi) : "l"(v));
}
__device__ __forceinline__ u64 fma2(u64 a, u64 b, u64 c) {
    u64 d; asm("fma.rn.f32x2 %0,%1,%2,%3;" : "=l"(d) : "l"(a), "l"(b), "l"(c)); return d;
}
__device__ __forceinline__ u64 mul2(u64 a, u64 b) {
    u64 d; asm("mul.rn.f32x2 %0,%1,%2;" : "=l"(d) : "l"(a), "l"(b)); return d;
}
__device__ __forceinline__ u64 add2(u64 a, u64 b) {
    u64 d; asm("add.rn.f32x2 %0,%1,%2;" : "=l"(d) : "l"(a), "l"(b)); return d;
}
__device__ __forceinline__ u64 sub2(u64 a, u64 b) {
    u64 d; asm("sub.rn.f32x2 %0,%1,%2;" : "=l"(d) : "l"(a), "l"(b)); return d;
}

__global__ __launch_bounds__(256, 4) void ssim_kernel(
    const float* __restrict__ A, const float* __restrict__ B,
    float* __restrict__ out)
{
    // Interleaved-quad layouts: each 16B quad = {X(2c), X(2c+1), Y(2c), Y(2c+1)}.
    __shared__ __align__(16) float sT[NQTOT * 4];        // input quads {A,B}
    __shared__ __align__(16) float hp0[IH * ROWOUT];     // h-filtered {A, B}
    __shared__ __align__(16) float hp1[IH * ROWOUT];     // h-filtered {A^2+B^2, AB}
    __shared__ float wsum[8];

    const int tid = threadIdx.x;
    const int plane = blockIdx.z;
    const int tx0 = blockIdx.x * TW;
    const int ty0 = blockIdx.y * TH;
    const float* a = A + (size_t)plane * IMG * IMG;
    const float* b = B + (size_t)plane * IMG * IMG;

    // ---- Stage haloed 42x42 tile as quads. All LDGs issued before stores
    //      (MLP=16); one STS.128 per quad, conflict-free. ----
    {
        float v[4][4];
#pragma unroll
        for (int j = 0; j < 4; j++) {
            int q = tid + j * 256;
            int r = q / NQIN;
            int cp = q - r * NQIN;
            int gy = ty0 - 5 + r;
            int gx0 = tx0 - 5 + 2 * cp;
            bool rowok = (q < NQTOT) && (gy >= 0) && (gy < IMG);
            const float* pa = a + (size_t)(gy * IMG);
            const float* pb = b + (size_t)(gy * IMG);
            v[j][0] = v[j][1] = v[j][2] = v[j][3] = 0.f;
            if (rowok && gx0 >= 0 && gx0 < IMG) {
                v[j][0] = __ldg(pa + gx0);
                v[j][2] = __ldg(pb + gx0);
            }
            if (rowok && gx0 + 1 >= 0 && gx0 + 1 < IMG) {
                v[j][1] = __ldg(pa + gx0 + 1);
                v[j][3] = __ldg(pb + gx0 + 1);
            }
        }
#pragma unroll
        for (int j = 0; j < 4; j++) {
            int q = tid + j * 256;
            if (q < NQTOT)
                *(float4*)&sT[q * 4] =
                    make_float4(v[j][0], v[j][1], v[j][2], v[j][3]);
        }
    }
    __syncthreads();

    // Packed (duplicated) weights.
    const u64 W0p = pack2(WV0, WV0), W1p = pack2(WV1, WV1), W2p = pack2(WV2, WV2);
    const u64 W3p = pack2(WV3, WV3), W4p = pack2(WV4, WV4), W5p = pack2(WV5, WV5);

    auto wp = [&](int t) -> u64 {
        switch (t) {
            case 0: case 10: return W0p;
            case 1: case 9:  return W1p;
            case 2: case 8:  return W2p;
            case 3: case 7:  return W3p;
            case 4: case 6:  return W4p;
            default:         return W5p;
        }
    };

    // Even/odd aligned-pair horizontal 11-tap conv: 4 outputs into 2 u64s.
    auto hplane = [&](const u64* q, u64& o01, u64& o23) {
        u64 E2a = fma2(W0p, add2(q[0], q[5]),
                  fma2(W2p, add2(q[1], q[4]),
                  mul2(W4p, add2(q[2], q[3]))));
        u64 E2b = fma2(W0p, add2(q[1], q[6]),
                  fma2(W2p, add2(q[2], q[5]),
                  mul2(W4p, add2(q[3], q[4]))));
        u64 Oa  = fma2(W1p, add2(q[0], q[4]),
                  fma2(W3p, add2(q[1], q[3]), mul2(W5p, q[2])));
        u64 Ob  = fma2(W1p, add2(q[1], q[5]),
                  fma2(W3p, add2(q[2], q[4]), mul2(W5p, q[3])));
        u64 Oc  = fma2(W1p, add2(q[2], q[6]),
                  fma2(W3p, add2(q[3], q[5]), mul2(W5p, q[4])));
        float oal, oah, obl, obh, ocl, och;
        unpack2(Oa, oal, oah);
        unpack2(Ob, obl, obh);
        unpack2(Oc, ocl, och);
        o01 = add2(E2a, pack2(oah, obl));
        o23 = add2(E2b, pack2(obh, ocl));
    };

    // ---- Horizontal pass: 42 rows x 8 groups of 4 outputs (336 items).
    //      7 LDS.128 in, 4 STS.128 out per group; zero re-reads. ----
    for (int g = tid; g < IH * 8; g += 256) {
        int r = g >> 3;
        int pg = g & 7;                   // output quads 2pg, 2pg+1
        const float* src = &sT[(r * NQIN + 2 * pg) * 4];
        u64 qa[7], qb[7];
#pragma unroll
        for (int j = 0; j < 7; j++) {
            ulonglong2 t = *(const ulonglong2*)(src + j * 4);
            qa[j] = t.x;                  // A pair
            qb[j] = t.y;                  // B pair
        }
        u64 rA0, rA1, rB0, rB1;
        hplane(qa, rA0, rA1);             // A
        hplane(qb, rB0, rB1);             // B
        float* d0 = &hp0[(r * NQOUT + 2 * pg) * 4];
        *(ulonglong2*)(d0)     = make_ulonglong2(rA0, rB0);
        *(ulonglong2*)(d0 + 4) = make_ulonglong2(rA1, rB1);
#pragma unroll
        for (int j = 0; j < 7; j++) {
            u64 ab = mul2(qa[j], qb[j]);
            qa[j] = fma2(qa[j], qa[j], mul2(qb[j], qb[j]));
            qb[j] = ab;
        }
        hplane(qa, rA0, rA1);             // A^2 + B^2
        hplane(qb, rB0, rB1);             // AB
        float* d1 = &hp1[(r * NQOUT + 2 * pg) * 4];
        *(ulonglong2*)(d1)     = make_ulonglong2(rA0, rB0);
        *(ulonglong2*)(d1 + 4) = make_ulonglong2(rA1, rB1);
    }
    __syncthreads();

    // ---- Vertical pass: 128 threads, each 2 cols x 4 rows, single sweep;
    //      2 LDS.128 per k feed all 4 plane accumulators. ----
    const float C1 = 0.0001f;
    const float C2 = 0.0009f;
    float accf = 0.f;
    if (tid < 128) {
        int xp = tid & 15;        // column pair 0..15
        int rg = tid >> 4;        // row group 0..7 (4 rows each)
        const float* p0 = &hp0[((rg * 4) * NQOUT + xp) * 4];
        const float* p1 = &hp1[((rg * 4) * NQOUT + xp) * 4];

        u64 zero = pack2(0.f, 0.f);
        u64 m1[4], m2[4], ss[4], e12[4];
#pragma unroll
        for (int i = 0; i < 4; i++) { m1[i] = m2[i] = ss[i] = e12[i] = zero; }

#pragma unroll
        for (int k = 0; k < 14; k++) {
            ulonglong2 t0 = *(const ulonglong2*)(p0 + k * ROWOUT);
            ulonglong2 t1 = *(const ulonglong2*)(p1 + k * ROWOUT);
#pragma unroll
            for (int i = 0; i < 4; i++) {
                int t = k - i;
                if (t >= 0 && t <= 10) {
                    u64 w = wp(t);
                    m1[i]  = fma2(w, t0.x, m1[i]);
                    m2[i]  = fma2(w, t0.y, m2[i]);
                    ss[i]  = fma2(w, t1.x, ss[i]);
                    e12[i] = fma2(w, t1.y, e12[i]);
                }
            }
        }

        const u64 c1p = pack2(C1, C1);
        const u64 c2p = pack2(C2, C2);
#pragma unroll
        for (int i = 0; i < 4; i++) {
            u64 m1s = mul2(m1[i], m1[i]);
            u64 m2s = mul2(m2[i], m2[i]);
            u64 m12 = mul2(m1[i], m2[i]);
            u64 mss = add2(m1s, m2s);
            u64 p2  = add2(m12, m12);
            u64 t2  = add2(e12[i], e12[i]);
            u64 n1  = add2(p2, c1p);
            u64 n2  = add2(sub2(t2, p2), c2p);
            u64 d1  = add2(mss, c1p);
            u64 d2  = add2(sub2(ss[i], mss), c2p);
            u64 num = mul2(n1, n2);
            u64 den = mul2(d1, d2);
            float nx, ny, dx, dy;
            unpack2(num, nx, ny);
            unpack2(den, dx, dy);
            accf += __fdividef(nx, dx) + __fdividef(ny, dy);
        }
    }

    // ---- Block reduction + single-pass finalize ----
#pragma unroll
    for (int off = 16; off > 0; off >>= 1)
        accf += __shfl_down_sync(0xffffffffu, accf, off);
    if ((tid & 31) == 0) wsum[tid >> 5] = accf;
    __syncthreads();
    if (tid == 0) {
        float bsum = 0.f;
#pragma unroll
        for (int i = 0; i < 8; i++) bsum += wsum[i];
        atomicAdd(&g_sum, (double)bsum);
        __threadfence();
        unsigned int cold = atomicAdd(&g_count, 1u);
        if (cold == GRID_TOTAL - 1) {
            __threadfence();
            double s = *((volatile double*)&g_sum);
            out[0] = (float)(s / (double)NPIX);
            g_sum = 0.0;
            g_count = 0u;
            __threadfence();
        }
    }
}

extern "C" void kernel_launch(void* const* d_in, const int* in_sizes, int n_in,
                              void* d_out, int out_size)
{
    const float* A = (const float*)d_in[0];
    const float* B = (const float*)d_in[1];
    float* out = (float*)d_out;
    dim3 grid(GRID_X, GRID_Y, GRID_Z);
    ssim_kernel<<<grid, 256>>>(A, B, out);
}

// round 13
// speedup vs baseline: 1.1771x; 1.1771x over previous
#include <cuda_runtime.h>

#define IMG 512
#define TW 32
#define TH 32
#define IW 42
#define IH 42
#define HROW 34
#define PL (IH * HROW)            // 1428 floats per hh plane
#define NPIX (16LL * 3 * 512 * 512)
#define GRID_X 16
#define GRID_Y 16
#define GRID_Z 48
#define GRID_TOTAL (GRID_X * GRID_Y * GRID_Z)

typedef unsigned long long u64;

__device__ double g_sum;
__device__ unsigned int g_count;

// Gaussian(sigma=1.5, K=11) weights, normalized — compile-time constants.
#define WV0 0.00102838f
#define WV1 0.00759876f
#define WV2 0.03600077f
#define WV3 0.10936069f
#define WV4 0.21300553f
#define WV5 0.26601172f

__device__ __forceinline__ u64 pack2(float lo, float hi) {
    u64 r; asm("mov.b64 %0,{%1,%2};" : "=l"(r) : "f"(lo), "f"(hi)); return r;
}
__device__ __forceinline__ void unpack2(u64 v, float& lo, float& hi) {
    asm("mov.b64 {%0,%1},%2;" : "=f"(lo), "=f"(hi) : "l"(v));
}
__device__ __forceinline__ u64 fma2(u64 a, u64 b, u64 c) {
    u64 d; asm("fma.rn.f32x2 %0,%1,%2,%3;" : "=l"(d) : "l"(a), "l"(b), "l"(c)); return d;
}
__device__ __forceinline__ u64 mul2(u64 a, u64 b) {
    u64 d; asm("mul.rn.f32x2 %0,%1,%2;" : "=l"(d) : "l"(a), "l"(b)); return d;
}
__device__ __forceinline__ u64 add2(u64 a, u64 b) {
    u64 d; asm("add.rn.f32x2 %0,%1,%2;" : "=l"(d) : "l"(a), "l"(b)); return d;
}
__device__ __forceinline__ u64 sub2(u64 a, u64 b) {
    u64 d; asm("sub.rn.f32x2 %0,%1,%2;" : "=l"(d) : "l"(a), "l"(b)); return d;
}

__global__ __launch_bounds__(256, 5) void ssim_kernel(
    const float* __restrict__ A, const float* __restrict__ B,
    float* __restrict__ out)
{
    // One pool; the staging area is reused as the v-pass exchange buffer.
    __shared__ __align__(16) float pool[2 * IH * IW + 4 * PL];
    __shared__ float wsum[8];
    float* sAf = pool;                       // IH*IW floats
    float* sBf = pool + IH * IW;             // IH*IW floats
    float* hhf = pool + 2 * IH * IW;         // 4 planes: A, B, A^2+B^2, AB
    u64*   ex  = (u64*)pool;                 // overlay (8192B <= 14112B)

    const int tid = threadIdx.x;
    const int plane = blockIdx.z;
    const int tx0 = blockIdx.x * TW;
    const int ty0 = blockIdx.y * TH;
    const float* a = A + (size_t)plane * IMG * IMG;
    const float* b = B + (size_t)plane * IMG * IMG;

    // ---- Stage haloed 42x42 tile, zero-padded. All LDGs issued before any
    //      STS (MLP=14). Incremental (r,c): one division total. ----
    {
        float va[7], vb[7];
        int r = tid / IW;
        int c = tid - r * IW;                 // 256 = 6*42 + 4
        int rj[7], cj[7];
#pragma unroll
        for (int j = 0; j < 7; j++) {
            rj[j] = r; cj[j] = c;
            r += 6; c += 4;
            if (c >= IW) { c -= IW; r += 1; }
        }
#pragma unroll
        for (int j = 0; j < 7; j++) {
            int gy = ty0 - 5 + rj[j];
            int gx = tx0 - 5 + cj[j];
            bool ok = (rj[j] < IH) &&
                      (gy >= 0) && (gy < IMG) && (gx >= 0) && (gx < IMG);
            size_t o = (size_t)(gy * IMG + gx);
            va[j] = 0.f; vb[j] = 0.f;
            if (ok) { va[j] = __ldg(a + o); vb[j] = __ldg(b + o); }
        }
#pragma unroll
        for (int j = 0; j < 7; j++) {
            if (rj[j] < IH) {
                int idx = rj[j] * IW + cj[j];
                sAf[idx] = va[j];
                sBf[idx] = vb[j];
            }
        }
    }
    __syncthreads();

    // Packed (duplicated) weights.
    const u64 W0p = pack2(WV0, WV0), W1p = pack2(WV1, WV1), W2p = pack2(WV2, WV2);
    const u64 W3p = pack2(WV3, WV3), W4p = pack2(WV4, WV4), W5p = pack2(WV5, WV5);

    auto wp = [&](int t) -> u64 {
        switch (t) {
            case 0: case 10: return W0p;
            case 1: case 9:  return W1p;
            case 2: case 8:  return W2p;
            case 3: case 7:  return W3p;
            case 4: case 6:  return W4p;
            default:         return W5p;
        }
    };

    // Even/odd aligned-pair horizontal 11-tap conv: 4 outputs per call.
    auto hplane = [&](const u64* q, float* dst) {
        u64 E2a = fma2(W0p, add2(q[0], q[5]),
                  fma2(W2p, add2(q[1], q[4]),
                  mul2(W4p, add2(q[2], q[3]))));
        u64 E2b = fma2(W0p, add2(q[1], q[6]),
                  fma2(W2p, add2(q[2], q[5]),
                  mul2(W4p, add2(q[3], q[4]))));
        u64 Oa  = fma2(W1p, add2(q[0], q[4]),
                  fma2(W3p, add2(q[1], q[3]), mul2(W5p, q[2])));
        u64 Ob  = fma2(W1p, add2(q[1], q[5]),
                  fma2(W3p, add2(q[2], q[4]), mul2(W5p, q[3])));
        u64 Oc  = fma2(W1p, add2(q[2], q[6]),
                  fma2(W3p, add2(q[3], q[5]), mul2(W5p, q[4])));
        float oal, oah, obl, obh, ocl, och;
        unpack2(Oa, oal, oah);
        unpack2(Ob, obl, obh);
        unpack2(Oc, ocl, och);
        *(u64*)(dst)     = add2(E2a, pack2(oah, obl));
        *(u64*)(dst + 2) = add2(E2b, pack2(obh, ocl));
    };

    // ---- Horizontal pass: 42 rows x 8 groups of 4 outputs (336 items).
    //      Single q[] buffer (re-read for products) keeps regs <= 48. ----
    auto hgroup = [&](int g) {
        int r = g >> 3;
        int c0 = (g & 7) << 2;
        const float* rowA = sAf + r * IW + c0;
        const float* rowB = sBf + r * IW + c0;
        float* dst = hhf + r * HROW + c0;
        u64 q[7];
#pragma unroll
        for (int j = 0; j < 7; j++) q[j] = *(const u64*)(rowA + 2 * j);
        hplane(q, dst);                                   // A
#pragma unroll
        for (int j = 0; j < 7; j++)
            q[j] = mul2(q[j], *(const u64*)(rowB + 2 * j));
        hplane(q, dst + 3 * PL);                          // AB
#pragma unroll
        for (int j = 0; j < 7; j++) q[j] = *(const u64*)(rowB + 2 * j);
        hplane(q, dst + PL);                              // B
#pragma unroll
        for (int j = 0; j < 7; j++) {
            u64 xa = *(const u64*)(rowA + 2 * j);
            q[j] = fma2(q[j], q[j], mul2(xa, xa));
        }
        hplane(q, dst + 2 * PL);                          // A^2 + B^2
    };
    hgroup(tid);
    if (tid < IH * 8 - 256) hgroup(tid + 256);
    __syncthreads();

    // ---- Vertical pass, plane-split over all 256 threads.
    //      Lower 128: planes A,B (m1,m2). Upper 128: planes SS,AB (ss,e12).
    //      Each 2 cols x 4 rows, one 14-iteration sweep. ----
    const float C1 = 0.0001f;
    const float C2 = 0.0009f;
    float accf = 0.f;
    {
        int half = tid >> 7;              // 0 = lower, 1 = upper
        int id   = tid & 127;
        int xp = id & 15;                 // column pair 0..15
        int rg = id >> 4;                 // row group 0..7 (4 rows each)
        const float* hp = hhf + (rg * 4) * HROW + 2 * xp + (half ? 2 * PL : 0);

        u64 zero = pack2(0.f, 0.f);
        u64 p0[4], p1[4];
#pragma unroll
        for (int i = 0; i < 4; i++) { p0[i] = p1[i] = zero; }
#pragma unroll
        for (int k = 0; k < 14; k++) {
            u64 L0 = *(const u64*)(hp + k * HROW);
            u64 L1 = *(const u64*)(hp + k * HROW + PL);
#pragma unroll
            for (int i = 0; i < 4; i++) {
                int t = k - i;
                if (t >= 0 && t <= 10) {
                    u64 w = wp(t);
                    p0[i] = fma2(w, L0, p0[i]);
                    p1[i] = fma2(w, L1, p1[i]);
                }
            }
        }
        // Upper half publishes ss (p0) and e12 (p1); conflict-free stride.
        if (half) {
#pragma unroll
            for (int i = 0; i < 4; i++) {
                ex[i * 128 + id]       = p0[i];
                ex[(4 + i) * 128 + id] = p1[i];
            }
        }
        __syncthreads();

        if (!half) {
            const u64 c1p = pack2(C1, C1);
            const u64 c2p = pack2(C2, C2);
#pragma unroll
            for (int i = 0; i < 4; i++) {
                u64 ssv  = ex[i * 128 + id];
                u64 e12v = ex[(4 + i) * 128 + id];
                u64 m1s = mul2(p0[i], p0[i]);
                u64 m2s = mul2(p1[i], p1[i]);
                u64 m12 = mul2(p0[i], p1[i]);
                u64 mss = add2(m1s, m2s);
                u64 pp2 = add2(m12, m12);
                u64 t2  = add2(e12v, e12v);
                u64 n1  = add2(pp2, c1p);
                u64 n2  = add2(sub2(t2, pp2), c2p);
                u64 d1  = add2(mss, c1p);
                u64 d2  = add2(sub2(ssv, mss), c2p);
                u64 num = mul2(n1, n2);
                u64 den = mul2(d1, d2);
                float nx, ny, dx, dy;
                unpack2(num, nx, ny);
                unpack2(den, dx, dy);
                accf += __fdividef(nx, dx) + __fdividef(ny, dy);
            }
        }
    }

    // ---- Block reduction + single-pass finalize ----
#pragma unroll
    for (int off = 16; off > 0; off >>= 1)
        accf += __shfl_down_sync(0xffffffffu, accf, off);
    if ((tid & 31) == 0) wsum[tid >> 5] = accf;
    __syncthreads();
    if (tid == 0) {
        float bsum = 0.f;
#pragma unroll
        for (int i = 0; i < 8; i++) bsum += wsum[i];
        atomicAdd(&g_sum, (double)bsum);
        __threadfence();
        unsigned int cold = atomicAdd(&g_count, 1u);
        if (cold == GRID_TOTAL - 1) {
            __threadfence();
            double s = *((volatile double*)&g_sum);
            out[0] = (float)(s / (double)NPIX);
            g_sum = 0.0;
            g_count = 0u;
            __threadfence();
        }
    }
}

extern "C" void kernel_launch(void* const* d_in, const int* in_sizes, int n_in,
                              void* d_out, int out_size)
{
    const float* A = (const float*)d_in[0];
    const float* B = (const float*)d_in[1];
    float* out = (float*)d_out;
    dim3 grid(GRID_X, GRID_Y, GRID_Z);
    ssim_kernel<<<grid, 256>>>(A, B, out);
}

// round 14
// speedup vs baseline: 1.2327x; 1.0472x over previous
#include <cuda_runtime.h>

#define IMG 512
#define TW 32
#define TH 32
#define IW 42
#define IH 42
#define HROW 34
#define PL (IH * HROW)            // 1428 floats per hh plane
#define NPIX (16LL * 3 * 512 * 512)
#define GRID_X 16
#define GRID_Y 16
#define GRID_Z 48
#define GRID_TOTAL (GRID_X * GRID_Y * GRID_Z)

typedef unsigned long long u64;

__device__ double g_sum;
__device__ unsigned int g_count;

// Gaussian(sigma=1.5, K=11) weights, normalized — compile-time constants.
#define WV0 0.00102838f
#define WV1 0.00759876f
#define WV2 0.03600077f
#define WV3 0.10936069f
#define WV4 0.21300553f
#define WV5 0.26601172f

__device__ __forceinline__ u64 pack2(float lo, float hi) {
    u64 r; asm("mov.b64 %0,{%1,%2};" : "=l"(r) : "f"(lo), "f"(hi)); return r;
}
__device__ __forceinline__ void unpack2(u64 v, float& lo, float& hi) {
    asm("mov.b64 {%0,%1},%2;" : "=f"(lo), "=f"(hi) : "l"(v));
}
__device__ __forceinline__ u64 fma2(u64 a, u64 b, u64 c) {
    u64 d; asm("fma.rn.f32x2 %0,%1,%2,%3;" : "=l"(d) : "l"(a), "l"(b), "l"(c)); return d;
}
__device__ __forceinline__ u64 mul2(u64 a, u64 b) {
    u64 d; asm("mul.rn.f32x2 %0,%1,%2;" : "=l"(d) : "l"(a), "l"(b)); return d;
}
__device__ __forceinline__ u64 add2(u64 a, u64 b) {
    u64 d; asm("add.rn.f32x2 %0,%1,%2;" : "=l"(d) : "l"(a), "l"(b)); return d;
}
__device__ __forceinline__ u64 sub2(u64 a, u64 b) {
    u64 d; asm("sub.rn.f32x2 %0,%1,%2;" : "=l"(d) : "l"(a), "l"(b)); return d;
}

__global__ __launch_bounds__(256, 5) void ssim_kernel(
    const float* __restrict__ A, const float* __restrict__ B,
    float* __restrict__ out)
{
    __shared__ __align__(16) float sA[IH][IW];
    __shared__ __align__(16) float sB[IH][IW];
    __shared__ __align__(16) float hh[4][IH][HROW];   // A, B, A^2+B^2, AB
    __shared__ float wsum[8];

    const int tid = threadIdx.x;
    const int plane = blockIdx.z;
    const int tx0 = blockIdx.x * TW;
    const int ty0 = blockIdx.y * TH;
    const float* a = A + (size_t)plane * IMG * IMG + (ty0 - 5) * IMG + (tx0 - 5);
    const float* b = B + (size_t)plane * IMG * IMG + (ty0 - 5) * IMG + (tx0 - 5);

    // ---- Stage haloed 42x42 tile, zero-padded. All LDGs issued before any
    //      STS (MLP=14). One division; incremental (r,c) thereafter. ----
    float* sAf = &sA[0][0];
    float* sBf = &sB[0][0];
    {
        float va[7], vb[7];
        int r = tid / IW;
        int c = tid - r * IW;                 // 256 = 6*42 + 4
        int rj[7], cj[7];
#pragma unroll
        for (int j = 0; j < 7; j++) {
            rj[j] = r; cj[j] = c;
            r += 6; c += 4;
            if (c >= IW) { c -= IW; r += 1; }
        }
#pragma unroll
        for (int j = 0; j < 7; j++) {
            int gy = ty0 - 5 + rj[j];
            int gx = tx0 - 5 + cj[j];
            bool ok = (rj[j] < IH) &&
                      (gy >= 0) && (gy < IMG) && (gx >= 0) && (gx < IMG);
            int o = rj[j] * IMG + cj[j];
            va[j] = 0.f; vb[j] = 0.f;
            if (ok) { va[j] = __ldg(a + o); vb[j] = __ldg(b + o); }
        }
#pragma unroll
        for (int j = 0; j < 7; j++) {
            if (rj[j] < IH) {
                int idx = rj[j] * IW + cj[j];
                sAf[idx] = va[j];
                sBf[idx] = vb[j];
            }
        }
    }
    __syncthreads();

    // Packed (duplicated) weights.
    const u64 W0p = pack2(WV0, WV0), W1p = pack2(WV1, WV1), W2p = pack2(WV2, WV2);
    const u64 W3p = pack2(WV3, WV3), W4p = pack2(WV4, WV4), W5p = pack2(WV5, WV5);

    auto wp = [&](int t) -> u64 {
        switch (t) {
            case 0: case 10: return W0p;
            case 1: case 9:  return W1p;
            case 2: case 8:  return W2p;
            case 3: case 7:  return W3p;
            case 4: case 6:  return W4p;
            default:         return W5p;
        }
    };

    // Even/odd aligned-pair horizontal 11-tap conv: 4 outputs per call.
    auto hplane = [&](const u64* q, float* dst) {
        u64 E2a = fma2(W0p, add2(q[0], q[5]),
                  fma2(W2p, add2(q[1], q[4]),
                  mul2(W4p, add2(q[2], q[3]))));
        u64 E2b = fma2(W0p, add2(q[1], q[6]),
                  fma2(W2p, add2(q[2], q[5]),
                  mul2(W4p, add2(q[3], q[4]))));
        u64 Oa  = fma2(W1p, add2(q[0], q[4]),
                  fma2(W3p, add2(q[1], q[3]), mul2(W5p, q[2])));
        u64 Ob  = fma2(W1p, add2(q[1], q[5]),
                  fma2(W3p, add2(q[2], q[4]), mul2(W5p, q[3])));
        u64 Oc  = fma2(W1p, add2(q[2], q[6]),
                  fma2(W3p, add2(q[3], q[5]), mul2(W5p, q[4])));
        float oal, oah, obl, obh, ocl, och;
        unpack2(Oa, oal, oah);
        unpack2(Ob, obl, obh);
        unpack2(Oc, ocl, och);
        *(u64*)(dst)     = add2(E2a, pack2(oah, obl));
        *(u64*)(dst + 2) = add2(E2b, pack2(obh, ocl));
    };

    // ---- Horizontal pass: 42 rows x 8 groups of 4 outputs (336 items).
    //      Single q[] buffer (re-read for products) keeps regs <= 48. ----
    auto hgroup = [&](int g) {
        int r = g >> 3;
        int c0 = (g & 7) << 2;
        const float* rowA = &sA[r][c0];
        const float* rowB = &sB[r][c0];
        float* dst = &hh[0][r][c0];
        u64 q[7];
#pragma unroll
        for (int j = 0; j < 7; j++) q[j] = *(const u64*)(rowA + 2 * j);
        hplane(q, dst);                                   // A
#pragma unroll
        for (int j = 0; j < 7; j++)
            q[j] = mul2(q[j], *(const u64*)(rowB + 2 * j));
        hplane(q, dst + 3 * PL);                          // AB
#pragma unroll
        for (int j = 0; j < 7; j++) q[j] = *(const u64*)(rowB + 2 * j);
        hplane(q, dst + PL);                              // B
#pragma unroll
        for (int j = 0; j < 7; j++) {
            u64 xa = *(const u64*)(rowA + 2 * j);
            q[j] = fma2(q[j], q[j], mul2(xa, xa));
        }
        hplane(q, dst + 2 * PL);                          // A^2 + B^2
    };
    hgroup(tid);
    if (tid < IH * 8 - 256) hgroup(tid + 256);            // 80 threads
    __syncthreads();

    // ---- Vertical pass: 128 threads, each 2 cols x 4 rows, TWO sweeps of
    //      2 planes each (same total LDS as one sweep; half the live regs). ----
    const float C1 = 0.0001f;
    const float C2 = 0.0009f;
    float accf = 0.f;
    if (tid < 128) {
        int xp = tid & 15;        // column pair 0..15
        int rg = tid >> 4;        // row group 0..7 (4 rows each)
        const float* hp = &hh[0][rg * 4][2 * xp];

        u64 zero = pack2(0.f, 0.f);
        u64 m1[4], m2[4];
#pragma unroll
        for (int i = 0; i < 4; i++) { m1[i] = m2[i] = zero; }
#pragma unroll
        for (int k = 0; k < 14; k++) {
            u64 L0 = *(const u64*)(hp + k * HROW);
            u64 L1 = *(const u64*)(hp + k * HROW + PL);
#pragma unroll
            for (int i = 0; i < 4; i++) {
                int t = k - i;
                if (t >= 0 && t <= 10) {
                    u64 w = wp(t);
                    m1[i] = fma2(w, L0, m1[i]);
                    m2[i] = fma2(w, L1, m2[i]);
                }
            }
        }
        u64 ss[4], e12[4];
#pragma unroll
        for (int i = 0; i < 4; i++) { ss[i] = e12[i] = zero; }
#pragma unroll
        for (int k = 0; k < 14; k++) {
            u64 L2 = *(const u64*)(hp + k * HROW + 2 * PL);
            u64 L3 = *(const u64*)(hp + k * HROW + 3 * PL);
#pragma unroll
            for (int i = 0; i < 4; i++) {
                int t = k - i;
                if (t >= 0 && t <= 10) {
                    u64 w = wp(t);
                    ss[i]  = fma2(w, L2, ss[i]);
                    e12[i] = fma2(w, L3, e12[i]);
                }
            }
        }

        const u64 c1p = pack2(C1, C1);
        const u64 c2p = pack2(C2, C2);
#pragma unroll
        for (int i = 0; i < 4; i++) {
            u64 m1s = mul2(m1[i], m1[i]);
            u64 m2s = mul2(m2[i], m2[i]);
            u64 m12 = mul2(m1[i], m2[i]);
            u64 mss = add2(m1s, m2s);
            u64 p2  = add2(m12, m12);
            u64 t2  = add2(e12[i], e12[i]);
            u64 n1  = add2(p2, c1p);
            u64 n2  = add2(sub2(t2, p2), c2p);
            u64 d1  = add2(mss, c1p);
            u64 d2  = add2(sub2(ss[i], mss), c2p);
            u64 num = mul2(n1, n2);
            u64 den = mul2(d1, d2);
            float nx, ny, dx, dy;
            unpack2(num, nx, ny);
            unpack2(den, dx, dy);
            accf += __fdividef(nx, dx) + __fdividef(ny, dy);
        }
    }

    // ---- Block reduction + single-pass finalize ----
#pragma unroll
    for (int off = 16; off > 0; off >>= 1)
        accf += __shfl_down_sync(0xffffffffu, accf, off);
    if ((tid & 31) == 0) wsum[tid >> 5] = accf;
    __syncthreads();
    if (tid == 0) {
        float bsum = 0.f;
#pragma unroll
        for (int i = 0; i < 8; i++) bsum += wsum[i];
        atomicAdd(&g_sum, (double)bsum);
        __threadfence();
        unsigned int cold = atomicAdd(&g_count, 1u);
        if (cold == GRID_TOTAL - 1) {
            __threadfence();
            double s = *((volatile double*)&g_sum);
            out[0] = (float)(s / (double)NPIX);
            g_sum = 0.0;
            g_count = 0u;
            __threadfence();
        }
    }
}

extern "C" void kernel_launch(void* const* d_in, const int* in_sizes, int n_in,
                              void* d_out, int out_size)
{
    const float* A = (const float*)d_in[0];
    const float* B = (const float*)d_in[1];
    float* out = (float*)d_out;
    dim3 grid(GRID_X, GRID_Y, GRID_Z);
    ssim_kernel<<<grid, 256>>>(A, B, out);
}